// round 2
// baseline (speedup 1.0000x reference)
#include <cuda_runtime.h>
#include <math.h>

#define NN 100000
#define EE 3200000
#define HDIM 256
#define BN_EPS 1e-5f

// ---------------- device scratch (static allocations only) ----------------
__device__ float g_z [ (size_t)NN * HDIM ];   // h + agg   (GEMM1 input)
__device__ float g_t [ (size_t)NN * HDIM ];   // MLP hidden (GEMM2 input)
__device__ float g_h1[ (size_t)NN * HDIM ];   // layer outputs (ping)
__device__ float g_h2[ (size_t)NN * HDIM ];   // layer outputs (pong)
__device__ int   g_counts[NN];                // histogram, later write cursor
__device__ int   g_rowptr[NN + 1];
__device__ int   g_esrc[EE];                  // src node ids grouped by dst
__device__ int   g_bsums[128];

// ---------------- CSR build ----------------
__global__ void k_zero_counts() {
    int i = blockIdx.x * blockDim.x + threadIdx.x;
    if (i < NN) g_counts[i] = 0;
}

__global__ void k_hist(const int* __restrict__ dst) {
    int e = blockIdx.x * blockDim.x + threadIdx.x;
    if (e < EE) atomicAdd(&g_counts[dst[e]], 1);
}

// inclusive scan per 1024-block; rowptr[i+1] = partial inclusive; bsums[b] = block total
__global__ void k_scan1() {
    __shared__ int sh[1024];
    int tid = threadIdx.x;
    int i = blockIdx.x * 1024 + tid;
    int v = (i < NN) ? g_counts[i] : 0;
    sh[tid] = v;
    __syncthreads();
    for (int off = 1; off < 1024; off <<= 1) {
        int t = (tid >= off) ? sh[tid - off] : 0;
        __syncthreads();
        sh[tid] += t;
        __syncthreads();
    }
    if (i < NN) g_rowptr[i + 1] = sh[tid];
    if (tid == 1023) g_bsums[blockIdx.x] = sh[tid];
}

// single-block exclusive scan of block sums (nb <= 98)
__global__ void k_scan2(int nb) {
    __shared__ int sh[128];
    int tid = threadIdx.x;
    int v = (tid < nb) ? g_bsums[tid] : 0;
    sh[tid] = v;
    __syncthreads();
    for (int off = 1; off < 128; off <<= 1) {
        int t = (tid >= off) ? sh[tid - off] : 0;
        __syncthreads();
        sh[tid] += t;
        __syncthreads();
    }
    if (tid < nb) g_bsums[tid] = sh[tid] - v;   // exclusive
}

__global__ void k_scan3() {
    int i = blockIdx.x * 1024 + threadIdx.x;
    if (i < NN) g_rowptr[i + 1] += g_bsums[blockIdx.x];
    if (i == 0) g_rowptr[0] = 0;
}

__global__ void k_cursor() {
    int i = blockIdx.x * blockDim.x + threadIdx.x;
    if (i < NN) g_counts[i] = g_rowptr[i];
}

__global__ void k_scatter(const int* __restrict__ src, const int* __restrict__ dst) {
    int e = blockIdx.x * blockDim.x + threadIdx.x;
    if (e < EE) {
        int p = atomicAdd(&g_counts[dst[e]], 1);
        g_esrc[p] = src[e];
    }
}

// ---------------- aggregation: z[i] = h[i] + sum_{j->i} h[j] ----------------
template <int FD>
__global__ void agg_kernel(const float* __restrict__ h, float* __restrict__ z) {
    constexpr int TPN = FD / 4;          // threads per node (float4 lanes)
    constexpr int NPB = 256 / TPN;       // nodes per 256-thread block
    int local = threadIdx.x / TPN;
    int lane  = threadIdx.x % TPN;
    int node  = blockIdx.x * NPB + local;
    if (node >= NN) return;

    const float4* h4 = (const float4*)h;
    int beg = g_rowptr[node];
    int end = g_rowptr[node + 1];

    float4 acc = h4[(size_t)node * TPN + lane];
    for (int e = beg; e < end; e++) {
        int s = g_esrc[e];
        float4 v = __ldg(&h4[(size_t)s * TPN + lane]);
        acc.x += v.x; acc.y += v.y; acc.z += v.z; acc.w += v.w;
    }
    ((float4*)z)[(size_t)node * TPN + lane] = acc;
}

// ---------------- fused GEMM: C[M,256] = A[M,K] @ B[K,256], BN/ReLU epilogue ----------------
// BNRELU: C = relu( (A@B + bias - mu) * g * rsqrt(var+eps) + be )
// else:   C = A@B + bias  (relu if RELU)
template <bool BNRELU, bool RELU>
__global__ void __launch_bounds__(256, 2)
gemm_kernel(const float* __restrict__ A, const float* __restrict__ B,
            float* __restrict__ C, int M, int K,
            const float* __restrict__ bias,
            const float* __restrict__ gamma, const float* __restrict__ beta,
            const float* __restrict__ mu,    const float* __restrict__ var) {
    const int BM = 128, BNc = 128, BK = 16;
    __shared__ float As[2][BK][BM];
    __shared__ float Bs[2][BK][BNc];

    int tid = threadIdx.x;
    int tx = tid & 15;        // 0..15 -> 8 cols each
    int ty = tid >> 4;        // 0..15 -> 8 rows each
    int m0 = blockIdx.y * BM;
    int n0 = blockIdx.x * BNc;

    float acc[8][8];
#pragma unroll
    for (int i = 0; i < 8; i++)
#pragma unroll
        for (int j = 0; j < 8; j++) acc[i][j] = 0.f;

    auto loadA = [&](int buf, int k0) {
#pragma unroll
        for (int r = 0; r < 2; r++) {
            int id = tid + r * 256;         // 0..511
            int m  = id >> 2;
            int kq = (id & 3) * 4;
            int row = m0 + m;
            float4 v = make_float4(0.f, 0.f, 0.f, 0.f);
            if (row < M) v = *(const float4*)(A + (size_t)row * K + k0 + kq);
            As[buf][kq + 0][m] = v.x;
            As[buf][kq + 1][m] = v.y;
            As[buf][kq + 2][m] = v.z;
            As[buf][kq + 3][m] = v.w;
        }
    };
    auto loadB = [&](int buf, int k0) {
#pragma unroll
        for (int r = 0; r < 2; r++) {
            int id = tid + r * 256;
            int k  = id >> 5;
            int nq = (id & 31) * 4;
            float4 v = *(const float4*)(B + (size_t)(k0 + k) * HDIM + n0 + nq);
            *(float4*)&Bs[buf][k][nq] = v;
        }
    };

    int nk = K / BK;
    loadA(0, 0);
    loadB(0, 0);
    __syncthreads();

    for (int kt = 0; kt < nk; kt++) {
        int cur = kt & 1;
        int nxt = cur ^ 1;
        if (kt + 1 < nk) {
            loadA(nxt, (kt + 1) * BK);
            loadB(nxt, (kt + 1) * BK);
        }
#pragma unroll
        for (int k = 0; k < BK; k++) {
            float a[8], b[8];
#pragma unroll
            for (int i = 0; i < 8; i++) a[i] = As[cur][k][ty * 8 + i];
#pragma unroll
            for (int j = 0; j < 8; j++) b[j] = Bs[cur][k][tx * 8 + j];
#pragma unroll
            for (int i = 0; i < 8; i++)
#pragma unroll
                for (int j = 0; j < 8; j++) acc[i][j] += a[i] * b[j];
        }
        __syncthreads();
    }

    // epilogue
    float scl[8], sft[8];
#pragma unroll
    for (int j = 0; j < 8; j++) {
        int col = n0 + tx * 8 + j;
        if (BNRELU) {
            float iv = rsqrtf(var[col] + BN_EPS);
            float s = gamma[col] * iv;
            scl[j] = s;
            sft[j] = (bias[col] - mu[col]) * s + beta[col];
        } else {
            scl[j] = 1.f;
            sft[j] = bias[col];
        }
    }
#pragma unroll
    for (int i = 0; i < 8; i++) {
        int row = m0 + ty * 8 + i;
        if (row < M) {
            float out[8];
#pragma unroll
            for (int j = 0; j < 8; j++) {
                float v = acc[i][j] * scl[j] + sft[j];
                if (BNRELU || RELU) v = fmaxf(v, 0.f);
                out[j] = v;
            }
            float* cp = C + (size_t)row * HDIM + n0 + tx * 8;
            *(float4*)(cp + 0) = make_float4(out[0], out[1], out[2], out[3]);
            *(float4*)(cp + 4) = make_float4(out[4], out[5], out[6], out[7]);
        }
    }
}

// ---------------- output head: out[N,2] = h @ W[256,2] + b ----------------
__global__ void out_kernel(const float* __restrict__ h, const float* __restrict__ W,
                           const float* __restrict__ b, float* __restrict__ out) {
    int warp = (blockIdx.x * blockDim.x + threadIdx.x) >> 5;
    int lane = threadIdx.x & 31;
    if (warp >= NN) return;
    const float* row = h + (size_t)warp * HDIM;
    float a0 = 0.f, a1 = 0.f;
#pragma unroll
    for (int k = lane; k < HDIM; k += 32) {
        float v = row[k];
        a0 += v * W[k * 2 + 0];
        a1 += v * W[k * 2 + 1];
    }
#pragma unroll
    for (int off = 16; off; off >>= 1) {
        a0 += __shfl_down_sync(0xffffffffu, a0, off);
        a1 += __shfl_down_sync(0xffffffffu, a1, off);
    }
    if (lane == 0) {
        out[warp * 2 + 0] = a0 + b[0];
        out[warp * 2 + 1] = a1 + b[1];
    }
}

// ---------------- launch ----------------
extern "C" void kernel_launch(void* const* d_in, const int* in_sizes, int n_in,
                              void* d_out, int out_size) {
    const float* x  = (const float*)d_in[0];
    const int*   ei = (const int*)d_in[1];
    const int* src = ei;
    const int* dst = ei + EE;

    const float* L[3][8];
    for (int l = 0; l < 3; l++)
        for (int p = 0; p < 8; p++)
            L[l][p] = (const float*)d_in[2 + l * 8 + p];
    // per layer order: W1, b1, g, be, mu, var, W2, b2
    const float* out_W = (const float*)d_in[26];
    const float* out_b = (const float*)d_in[27];

    float *z, *t, *h1, *h2;
    cudaGetSymbolAddress((void**)&z,  g_z);
    cudaGetSymbolAddress((void**)&t,  g_t);
    cudaGetSymbolAddress((void**)&h1, g_h1);
    cudaGetSymbolAddress((void**)&h2, g_h2);

    // ---- CSR build ----
    int nb_scan = (NN + 1023) / 1024;               // 98
    k_zero_counts<<<(NN + 255) / 256, 256>>>();
    k_hist<<<(EE + 255) / 256, 256>>>(dst);
    k_scan1<<<nb_scan, 1024>>>();
    k_scan2<<<1, 128>>>(nb_scan);
    k_scan3<<<nb_scan, 1024>>>();
    k_cursor<<<(NN + 255) / 256, 256>>>();
    k_scatter<<<(EE + 255) / 256, 256>>>(src, dst);

    dim3 gg(2, (NN + 127) / 128);   // 2 col tiles x 782 row tiles

    // ---- layer 1 (fin=128) ----
    agg_kernel<128><<<(NN + 7) / 8, 256>>>(x, z);
    gemm_kernel<true, true><<<gg, 256>>>(z, L[0][0], t, NN, 128,
                                         L[0][1], L[0][2], L[0][3], L[0][4], L[0][5]);
    gemm_kernel<false, true><<<gg, 256>>>(t, L[0][6], h1, NN, 256,
                                          L[0][7], nullptr, nullptr, nullptr, nullptr);
    // ---- layer 2 ----
    agg_kernel<256><<<(NN + 3) / 4, 256>>>(h1, z);
    gemm_kernel<true, true><<<gg, 256>>>(z, L[1][0], t, NN, 256,
                                         L[1][1], L[1][2], L[1][3], L[1][4], L[1][5]);
    gemm_kernel<false, true><<<gg, 256>>>(t, L[1][6], h2, NN, 256,
                                          L[1][7], nullptr, nullptr, nullptr, nullptr);
    // ---- layer 3 (no final relu) ----
    agg_kernel<256><<<(NN + 3) / 4, 256>>>(h2, z);
    gemm_kernel<true, true><<<gg, 256>>>(z, L[2][0], t, NN, 256,
                                         L[2][1], L[2][2], L[2][3], L[2][4], L[2][5]);
    gemm_kernel<false, false><<<gg, 256>>>(t, L[2][6], h1, NN, 256,
                                           L[2][7], nullptr, nullptr, nullptr, nullptr);

    // ---- head ----
    out_kernel<<<(NN * 32 + 255) / 256, 256>>>(h1, out_W, out_b, (float*)d_out);
}

// round 4
// speedup vs baseline: 1.7006x; 1.7006x over previous
#include <cuda_runtime.h>
#include <cuda_bf16.h>
#include <cstdint>
#include <math.h>

#define NN 100000
#define EE 3200000
#define HDIM 256
#define BN_EPS 1e-5f

// ---------------- device scratch ----------------
__device__ __nv_bfloat16 g_zhi[(size_t)NN * HDIM];
__device__ __nv_bfloat16 g_zlo[(size_t)NN * HDIM];
__device__ __nv_bfloat16 g_thi[(size_t)NN * HDIM];
__device__ __nv_bfloat16 g_tlo[(size_t)NN * HDIM];
__device__ float         g_h  [(size_t)NN * HDIM];
__device__ __nv_bfloat16 g_w  [6][2][HDIM * HDIM];   // W [K][256] bf16 hi/lo (k-major)
__device__ int g_counts[NN];
__device__ int g_rowptr[NN + 1];
__device__ int g_esrc[EE];
__device__ int g_bsums[128];

// ---------------- helpers ----------------
__device__ __forceinline__ uint32_t smem_u32(const void* p) {
    uint32_t a;
    asm("{ .reg .u64 t; cvta.to.shared.u64 t, %1; cvt.u32.u64 %0, t; }" : "=r"(a) : "l"(p));
    return a;
}
__device__ __forceinline__ void mma16816(float* c, const uint32_t* a, const uint32_t* b) {
    asm volatile(
        "mma.sync.aligned.m16n8k16.row.col.f32.bf16.bf16.f32 "
        "{%0,%1,%2,%3}, {%4,%5,%6,%7}, {%8,%9}, {%0,%1,%2,%3};"
        : "+f"(c[0]), "+f"(c[1]), "+f"(c[2]), "+f"(c[3])
        : "r"(a[0]), "r"(a[1]), "r"(a[2]), "r"(a[3]), "r"(b[0]), "r"(b[1]));
}
__device__ __forceinline__ void ldmx4(uint32_t* r, uint32_t addr) {
    asm volatile("ldmatrix.sync.aligned.m8n8.x4.shared.b16 {%0,%1,%2,%3}, [%4];"
                 : "=r"(r[0]), "=r"(r[1]), "=r"(r[2]), "=r"(r[3]) : "r"(addr));
}
__device__ __forceinline__ void ldmx2t(uint32_t* r, uint32_t addr) {
    asm volatile("ldmatrix.sync.aligned.m8n8.x2.trans.shared.b16 {%0,%1}, [%2];"
                 : "=r"(r[0]), "=r"(r[1]) : "r"(addr));
}
__device__ __forceinline__ void cpasync16(uint32_t saddr, const void* gaddr, uint32_t sz) {
    asm volatile("cp.async.ca.shared.global [%0], [%1], 16, %2;"
                 :: "r"(saddr), "l"(gaddr), "r"(sz));
}
__device__ __forceinline__ uint32_t pack_hi(float v0, float v1, float& r0, float& r1) {
    __nv_bfloat16 h0 = __float2bfloat16_rn(v0);
    __nv_bfloat16 h1 = __float2bfloat16_rn(v1);
    r0 = v0 - __bfloat162float(h0);
    r1 = v1 - __bfloat162float(h1);
    __nv_bfloat162 p = __halves2bfloat162(h0, h1);
    return *(uint32_t*)&p;
}

// ---------------- CSR build ----------------
__global__ void k_zero_counts() {
    int i = blockIdx.x * blockDim.x + threadIdx.x;
    if (i < NN) g_counts[i] = 0;
}
__global__ void k_hist(const int* __restrict__ dst) {
    int e = blockIdx.x * blockDim.x + threadIdx.x;
    if (e < EE) atomicAdd(&g_counts[dst[e]], 1);
}
__global__ void k_scan1() {
    __shared__ int sh[1024];
    int tid = threadIdx.x;
    int i = blockIdx.x * 1024 + tid;
    int v = (i < NN) ? g_counts[i] : 0;
    sh[tid] = v;
    __syncthreads();
    for (int off = 1; off < 1024; off <<= 1) {
        int t = (tid >= off) ? sh[tid - off] : 0;
        __syncthreads();
        sh[tid] += t;
        __syncthreads();
    }
    if (i < NN) g_rowptr[i + 1] = sh[tid];
    if (tid == 1023) g_bsums[blockIdx.x] = sh[tid];
}
__global__ void k_scan2(int nb) {
    __shared__ int sh[128];
    int tid = threadIdx.x;
    int v = (tid < nb) ? g_bsums[tid] : 0;
    sh[tid] = v;
    __syncthreads();
    for (int off = 1; off < 128; off <<= 1) {
        int t = (tid >= off) ? sh[tid - off] : 0;
        __syncthreads();
        sh[tid] += t;
        __syncthreads();
    }
    if (tid < nb) g_bsums[tid] = sh[tid] - v;
}
__global__ void k_scan3() {
    int i = blockIdx.x * 1024 + threadIdx.x;
    if (i < NN) g_rowptr[i + 1] += g_bsums[blockIdx.x];
    if (i == 0) g_rowptr[0] = 0;
}
__global__ void k_cursor() {
    int i = blockIdx.x * blockDim.x + threadIdx.x;
    if (i < NN) g_counts[i] = g_rowptr[i];
}
__global__ void k_scatter(const int* __restrict__ src, const int* __restrict__ dst) {
    int e = blockIdx.x * blockDim.x + threadIdx.x;
    if (e < EE) {
        int p = atomicAdd(&g_counts[dst[e]], 1);
        g_esrc[p] = src[e];
    }
}

// ---------------- weight convert: W[K,256] fp32 -> bf16 hi/lo (same layout) ----------------
__global__ void k_wconv(const float* __restrict__ W, int K,
                        __nv_bfloat16* __restrict__ hi, __nv_bfloat16* __restrict__ lo) {
    int idx = blockIdx.x * blockDim.x + threadIdx.x;
    if (idx >= K * 256) return;
    float w = W[idx];
    __nv_bfloat16 h = __float2bfloat16_rn(w);
    hi[idx] = h;
    lo[idx] = __float2bfloat16_rn(w - __bfloat162float(h));
}

// ---------------- aggregation: z[i] = h[i] + sum_{j->i} h[j], emit bf16 hi/lo ----------------
template <int FD>
__global__ void agg_kernel(const float* __restrict__ h,
                           __nv_bfloat16* __restrict__ zhi, __nv_bfloat16* __restrict__ zlo) {
    constexpr int TPN = FD / 4;
    constexpr int NPB = 256 / TPN;
    int local = threadIdx.x / TPN;
    int lane  = threadIdx.x % TPN;
    int node  = blockIdx.x * NPB + local;
    if (node >= NN) return;

    const float4* h4 = (const float4*)h;
    int beg = g_rowptr[node];
    int end = g_rowptr[node + 1];

    float4 acc = h4[(size_t)node * TPN + lane];
    for (int e = beg; e < end; e++) {
        int s = g_esrc[e];
        float4 v = __ldg(&h4[(size_t)s * TPN + lane]);
        acc.x += v.x; acc.y += v.y; acc.z += v.z; acc.w += v.w;
    }
    float vv[4] = {acc.x, acc.y, acc.z, acc.w};
    __nv_bfloat16 hh[4], ll[4];
#pragma unroll
    for (int q = 0; q < 4; q++) {
        hh[q] = __float2bfloat16_rn(vv[q]);
        ll[q] = __float2bfloat16_rn(vv[q] - __bfloat162float(hh[q]));
    }
    size_t off = (size_t)node * FD + lane * 4;
    *(uint2*)(zhi + off) = *(uint2*)hh;
    *(uint2*)(zlo + off) = *(uint2*)ll;
}

// ---------------- mma.sync GEMM: C[M,256] = A[M,K] @ W[K,256], 3-term bf16 split ----------------
// MODE 0: BN + ReLU -> bf16 hi/lo   MODE 1: bias + ReLU -> fp32   MODE 2: bias -> fp32
static constexpr int STG_STRIDE = 32768;   // bytes per pipeline stage
static constexpr int A_LO = 8192, B_HI = 16384, B_LO = 24576;
static constexpr int SM_SCL = 65536, SM_SFT = 66560;
static constexpr int SMEM_BYTES = 67584;

template <int K, int MODE>
__global__ void __launch_bounds__(256, 1)
gemm_mma(const __nv_bfloat16* __restrict__ Ah, const __nv_bfloat16* __restrict__ Al,
         const __nv_bfloat16* __restrict__ Bh, const __nv_bfloat16* __restrict__ Bl,
         float* __restrict__ Cf,
         __nv_bfloat16* __restrict__ Chi, __nv_bfloat16* __restrict__ Clo,
         const float* __restrict__ bias,
         const float* __restrict__ gamma, const float* __restrict__ beta,
         const float* __restrict__ mu,    const float* __restrict__ var) {
    extern __shared__ char sc[];
    uint32_t sb = smem_u32(sc);
    constexpr int NST = K / 32;

    int tid = threadIdx.x;
    int wid = tid >> 5;
    int lane = tid & 31;
    int wm = wid >> 2;       // 0..1
    int wn = wid & 3;        // 0..3
    int n0 = blockIdx.x * 128;
    int m0 = blockIdx.y * 128;

    // epilogue params
    if (tid < 256) {
        float s, t;
        if (MODE == 0) {
            float iv = rsqrtf(var[tid] + BN_EPS);
            s = gamma[tid] * iv;
            t = (bias[tid] - mu[tid]) * s + beta[tid];
        } else {
            s = 1.f;
            t = bias[tid];
        }
        ((float*)(sc + SM_SCL))[tid] = s;
        ((float*)(sc + SM_SFT))[tid] = t;
    }

    // -------- stage loader --------
    auto load_stage = [&](int s) {
        int buf = s & 1;
        uint32_t ss = sb + buf * STG_STRIDE;
        int k0 = s * 32;
#pragma unroll
        for (int r = 0; r < 2; r++) {
            int idx = tid + r * 256;
            int m = idx >> 2, c = idx & 3;
            uint32_t phys = m * 64 + ((c ^ ((m >> 1) & 3)) * 16);
            int gm = m0 + m;
            uint32_t sz = (gm < NN) ? 16u : 0u;
            size_t go = (size_t)(gm < NN ? gm : 0) * K + k0 + c * 8;
            cpasync16(ss + phys,        Ah + go, sz);
            cpasync16(ss + A_LO + phys, Al + go, sz);
        }
#pragma unroll
        for (int r = 0; r < 2; r++) {
            int idx = tid + r * 256;
            int kk = idx >> 4, j = idx & 15;
            uint32_t phys = kk * 256 + ((j ^ (kk & 7)) * 16);
            size_t go = (size_t)(k0 + kk) * 256 + n0 + j * 8;
            cpasync16(ss + B_HI + phys, Bh + go, 16);
            cpasync16(ss + B_LO + phys, Bl + go, 16);
        }
        asm volatile("cp.async.commit_group;" ::: "memory");
    };

    // -------- ldmatrix address precompute --------
    int ml = lane & 15, chalf = lane >> 4;
    uint32_t a_off[4];
    int a_sw[4];
#pragma unroll
    for (int t = 0; t < 4; t++) {
        int mrow = wm * 64 + t * 16 + ml;
        a_off[t] = mrow * 64;
        a_sw[t] = (mrow >> 1) & 3;
    }
    uint32_t b_off[4];
#pragma unroll
    for (int u = 0; u < 4; u++) {
        int j = wn * 4 + u;
        b_off[u] = (lane & 15) * 256 + ((j ^ (lane & 7)) * 16);
    }

    float acc[4][4][4];
#pragma unroll
    for (int t = 0; t < 4; t++)
#pragma unroll
        for (int u = 0; u < 4; u++)
#pragma unroll
            for (int r = 0; r < 4; r++) acc[t][u][r] = 0.f;

    load_stage(0);
    load_stage(1);

    for (int s = 0; s < NST; s++) {
        if (s + 1 < NST) asm volatile("cp.async.wait_group 1;" ::: "memory");
        else             asm volatile("cp.async.wait_group 0;" ::: "memory");
        __syncthreads();

        uint32_t ss = sb + (s & 1) * STG_STRIDE;
#pragma unroll
        for (int ks = 0; ks < 2; ks++) {
            uint32_t ah[4][4], al[4][4], bh[4][2], bl[4][2];
#pragma unroll
            for (int t = 0; t < 4; t++) {
                uint32_t co = (uint32_t)(((ks * 2 + chalf) ^ a_sw[t]) * 16);
                ldmx4(ah[t], ss + a_off[t] + co);
                ldmx4(al[t], ss + A_LO + a_off[t] + co);
            }
#pragma unroll
            for (int u = 0; u < 4; u++) {
                ldmx2t(bh[u], ss + B_HI + b_off[u] + ks * 4096);
                ldmx2t(bl[u], ss + B_LO + b_off[u] + ks * 4096);
            }
#pragma unroll
            for (int t = 0; t < 4; t++)
#pragma unroll
                for (int u = 0; u < 4; u++) {
                    mma16816(acc[t][u], ah[t], bh[u]);
                    mma16816(acc[t][u], ah[t], bl[u]);
                    mma16816(acc[t][u], al[t], bh[u]);
                }
        }
        __syncthreads();
        if (s + 2 < NST) load_stage(s + 2);
    }

    // -------- epilogue --------
    const float* scl = (const float*)(sc + SM_SCL);
    const float* sft = (const float*)(sc + SM_SFT);
    int g = lane >> 2, tg = lane & 3;
#pragma unroll
    for (int t = 0; t < 4; t++) {
        int row0 = m0 + wm * 64 + t * 16 + g;
#pragma unroll
        for (int u = 0; u < 4; u++) {
            int col = n0 + wn * 32 + u * 8 + tg * 2;
            float s0 = scl[col], s1 = scl[col + 1];
            float f0 = sft[col], f1 = sft[col + 1];
#pragma unroll
            for (int half = 0; half < 2; half++) {
                int row = row0 + half * 8;
                if (row >= NN) continue;
                float v0 = acc[t][u][half * 2 + 0] * s0 + f0;
                float v1 = acc[t][u][half * 2 + 1] * s1 + f1;
                if (MODE != 2) { v0 = fmaxf(v0, 0.f); v1 = fmaxf(v1, 0.f); }
                size_t o = (size_t)row * 256 + col;
                if (MODE == 0) {
                    float r0, r1;
                    uint32_t hp = pack_hi(v0, v1, r0, r1);
                    __nv_bfloat162 lp2 = __halves2bfloat162(
                        __float2bfloat16_rn(r0), __float2bfloat16_rn(r1));
                    *(uint32_t*)(Chi + o) = hp;
                    *(uint32_t*)(Clo + o) = *(uint32_t*)&lp2;
                } else {
                    float2 v = make_float2(v0, v1);
                    *(float2*)(Cf + o) = v;
                }
            }
        }
    }
}

// ---------------- output head: out[N,2] = h @ W[256,2] + b ----------------
__global__ void out_kernel(const float* __restrict__ h, const float* __restrict__ W,
                           const float* __restrict__ b, float* __restrict__ out) {
    int warp = (blockIdx.x * blockDim.x + threadIdx.x) >> 5;
    int lane = threadIdx.x & 31;
    if (warp >= NN) return;
    const float* row = h + (size_t)warp * HDIM;
    float a0 = 0.f, a1 = 0.f;
#pragma unroll
    for (int k = lane; k < HDIM; k += 32) {
        float v = row[k];
        a0 += v * W[k * 2 + 0];
        a1 += v * W[k * 2 + 1];
    }
#pragma unroll
    for (int off = 16; off; off >>= 1) {
        a0 += __shfl_down_sync(0xffffffffu, a0, off);
        a1 += __shfl_down_sync(0xffffffffu, a1, off);
    }
    if (lane == 0) {
        out[warp * 2 + 0] = a0 + b[0];
        out[warp * 2 + 1] = a1 + b[1];
    }
}

// ---------------- launch ----------------
extern "C" void kernel_launch(void* const* d_in, const int* in_sizes, int n_in,
                              void* d_out, int out_size) {
    const float* x  = (const float*)d_in[0];
    const int*   ei = (const int*)d_in[1];
    const int* src = ei;
    const int* dst = ei + EE;

    const float* L[3][8];
    for (int l = 0; l < 3; l++)
        for (int p = 0; p < 8; p++)
            L[l][p] = (const float*)d_in[2 + l * 8 + p];
    const float* out_W = (const float*)d_in[26];
    const float* out_b = (const float*)d_in[27];

    __nv_bfloat16 *zhi, *zlo, *thi, *tlo, *wt;
    float* h;
    cudaGetSymbolAddress((void**)&zhi, g_zhi);
    cudaGetSymbolAddress((void**)&zlo, g_zlo);
    cudaGetSymbolAddress((void**)&thi, g_thi);
    cudaGetSymbolAddress((void**)&tlo, g_tlo);
    cudaGetSymbolAddress((void**)&h,   g_h);
    cudaGetSymbolAddress((void**)&wt,  g_w);
    auto WT = [&](int w, int hl) { return wt + ((size_t)w * 2 + hl) * HDIM * HDIM; };

    cudaFuncSetAttribute(gemm_mma<128, 0>, cudaFuncAttributeMaxDynamicSharedMemorySize, SMEM_BYTES);
    cudaFuncSetAttribute(gemm_mma<256, 0>, cudaFuncAttributeMaxDynamicSharedMemorySize, SMEM_BYTES);
    cudaFuncSetAttribute(gemm_mma<256, 1>, cudaFuncAttributeMaxDynamicSharedMemorySize, SMEM_BYTES);
    cudaFuncSetAttribute(gemm_mma<256, 2>, cudaFuncAttributeMaxDynamicSharedMemorySize, SMEM_BYTES);

    // ---- weight conversion ----
    k_wconv<<<(128 * 256 + 255) / 256, 256>>>(L[0][0], 128, WT(0, 0), WT(0, 1));
    k_wconv<<<(256 * 256 + 255) / 256, 256>>>(L[0][6], 256, WT(1, 0), WT(1, 1));
    k_wconv<<<(256 * 256 + 255) / 256, 256>>>(L[1][0], 256, WT(2, 0), WT(2, 1));
    k_wconv<<<(256 * 256 + 255) / 256, 256>>>(L[1][6], 256, WT(3, 0), WT(3, 1));
    k_wconv<<<(256 * 256 + 255) / 256, 256>>>(L[2][0], 256, WT(4, 0), WT(4, 1));
    k_wconv<<<(256 * 256 + 255) / 256, 256>>>(L[2][6], 256, WT(5, 0), WT(5, 1));

    // ---- CSR build ----
    int nb_scan = (NN + 1023) / 1024;
    k_zero_counts<<<(NN + 255) / 256, 256>>>();
    k_hist<<<(EE + 255) / 256, 256>>>(dst);
    k_scan1<<<nb_scan, 1024>>>();
    k_scan2<<<1, 128>>>(nb_scan);
    k_scan3<<<nb_scan, 1024>>>();
    k_cursor<<<(NN + 255) / 256, 256>>>();
    k_scatter<<<(EE + 255) / 256, 256>>>(src, dst);

    dim3 gg(2, (NN + 127) / 128);   // 2 n-tiles x 782 m-tiles

    // ---- layer 1 ----
    agg_kernel<128><<<(NN + 7) / 8, 256>>>(x, zhi, zlo);
    gemm_mma<128, 0><<<gg, 256, SMEM_BYTES>>>(zhi, zlo, WT(0, 0), WT(0, 1),
        nullptr, thi, tlo, L[0][1], L[0][2], L[0][3], L[0][4], L[0][5]);
    gemm_mma<256, 1><<<gg, 256, SMEM_BYTES>>>(thi, tlo, WT(1, 0), WT(1, 1),
        h, nullptr, nullptr, L[0][7], nullptr, nullptr, nullptr, nullptr);

    // ---- layer 2 ----
    agg_kernel<256><<<(NN + 3) / 4, 256>>>(h, zhi, zlo);
    gemm_mma<256, 0><<<gg, 256, SMEM_BYTES>>>(zhi, zlo, WT(2, 0), WT(2, 1),
        nullptr, thi, tlo, L[1][1], L[1][2], L[1][3], L[1][4], L[1][5]);
    gemm_mma<256, 1><<<gg, 256, SMEM_BYTES>>>(thi, tlo, WT(3, 0), WT(3, 1),
        h, nullptr, nullptr, L[1][7], nullptr, nullptr, nullptr, nullptr);

    // ---- layer 3 ----
    agg_kernel<256><<<(NN + 3) / 4, 256>>>(h, zhi, zlo);
    gemm_mma<256, 0><<<gg, 256, SMEM_BYTES>>>(zhi, zlo, WT(4, 0), WT(4, 1),
        nullptr, thi, tlo, L[2][1], L[2][2], L[2][3], L[2][4], L[2][5]);
    gemm_mma<256, 2><<<gg, 256, SMEM_BYTES>>>(thi, tlo, WT(5, 0), WT(5, 1),
        h, nullptr, nullptr, L[2][7], nullptr, nullptr, nullptr, nullptr);

    // ---- head ----
    out_kernel<<<(NN * 32 + 255) / 256, 256>>>(h, out_W, out_b, (float*)d_out);
}